// round 2
// baseline (speedup 1.0000x reference)
#include <cuda_runtime.h>

// Problem-fixed shapes (from reference_code)
#define N_NODES 100000
#define E_EDGES 1600000
#define FIN  16
#define FMID 32
#define FOUT 16

// ---------------- device scratch (no allocations allowed) ----------------
__device__ int   g_row[E_EDGES];
__device__ int   g_col[E_EDGES];
__device__ float g_dinv[N_NODES];           // deg accumulator, then rsqrt in place
__device__ float g_h1[N_NODES * FMID];      // x @ W1
__device__ float g_o1[N_NODES * FMID];      // segment-sum + b1 (pre-relu)
__device__ float g_h2[N_NODES * FOUT];      // relu(o1) @ W2
__device__ float g_o2[N_NODES * FOUT];      // segment-sum + b2 (pre-relu)
__device__ int   g_is64;                    // edge_index dtype flag

// ---------------- kernels ----------------

// deg init = 1.0 (accounts for the self-loop on every node)
__global__ void k_init_deg() {
    int i = blockIdx.x * blockDim.x + threadIdx.x;
    if (i < N_NODES) g_dinv[i] = 1.0f;
}

// Detect whether edge_index is int64 (odd 32-bit words all zero) or int32.
__global__ void k_detect(const unsigned int* __restrict__ words) {
    __shared__ unsigned int s_or;
    if (threadIdx.x == 0) s_or = 0u;
    __syncthreads();
    unsigned int acc = 0u;
    // sample 8192 odd-position words (within bounds for both dtypes)
    for (int j = threadIdx.x; j < 8192; j += blockDim.x)
        acc |= words[2 * j + 1];
    atomicOr(&s_or, acc);
    __syncthreads();
    if (threadIdx.x == 0) g_is64 = (s_or == 0u) ? 1 : 0;
}

// Convert edges to int32 scratch + accumulate degree of col.
__global__ void k_edges(const void* __restrict__ edge_raw, int E) {
    int e = blockIdx.x * blockDim.x + threadIdx.x;
    if (e >= E) return;
    int r, c;
    if (g_is64) {
        const long long* p = (const long long*)edge_raw;
        r = (int)p[e];
        c = (int)p[E + e];
    } else {
        const int* p = (const int*)edge_raw;
        r = p[e];
        c = p[E + e];
    }
    g_row[e] = r;
    g_col[e] = c;
    atomicAdd(&g_dinv[c], 1.0f);
}

__global__ void k_rsqrt() {
    int i = blockIdx.x * blockDim.x + threadIdx.x;
    if (i < N_NODES) g_dinv[i] = rsqrtf(g_dinv[i]);   // deg >= 1 always
}

// h1 = x @ W1 ; o1 = h1 * dinv^2 + b1  (self-loop contribution + bias)
// thread = (node, feature): node broadcast within warp, coalesced writes.
__global__ void k_lin1(const float* __restrict__ x,
                       const float* __restrict__ W1,
                       const float* __restrict__ b1) {
    __shared__ float sW[FIN * FMID];
    for (int t = threadIdx.x; t < FIN * FMID; t += blockDim.x) sW[t] = W1[t];
    __syncthreads();
    int idx = blockIdx.x * blockDim.x + threadIdx.x;
    if (idx >= N_NODES * FMID) return;
    int i = idx >> 5;         // FMID == 32
    int f = idx & 31;
    float acc = 0.0f;
    #pragma unroll
    for (int k = 0; k < FIN; k++)
        acc = fmaf(x[i * FIN + k], sW[k * FMID + f], acc);
    g_h1[idx] = acc;
    float d = g_dinv[i];
    g_o1[idx] = fmaf(acc, d * d, b1[f]);
}

// Layer-1 edge scatter: one warp per edge, lane = feature (32 == FMID).
__global__ void k_scatter1(int E) {
    long long idx = (long long)blockIdx.x * blockDim.x + threadIdx.x;
    if (idx >= (long long)E * FMID) return;
    int e = (int)(idx >> 5);
    int f = (int)(idx & 31);
    int r = g_row[e];
    int c = g_col[e];
    float n = g_dinv[r] * g_dinv[c];
    atomicAdd(&g_o1[c * FMID + f], g_h1[r * FMID + f] * n);
}

// h2 = relu(o1) @ W2 ; o2 = h2 * dinv^2 + b2
__global__ void k_lin2(const float* __restrict__ W2,
                       const float* __restrict__ b2) {
    __shared__ float sW[FMID * FOUT];
    for (int t = threadIdx.x; t < FMID * FOUT; t += blockDim.x) sW[t] = W2[t];
    __syncthreads();
    int idx = blockIdx.x * blockDim.x + threadIdx.x;
    if (idx >= N_NODES * FOUT) return;
    int i = idx >> 4;         // FOUT == 16
    int f = idx & 15;
    float acc = 0.0f;
    #pragma unroll
    for (int k = 0; k < FMID; k++) {
        float v = fmaxf(g_o1[i * FMID + k], 0.0f);
        acc = fmaf(v, sW[k * FOUT + f], acc);
    }
    g_h2[idx] = acc;
    float d = g_dinv[i];
    g_o2[idx] = fmaf(acc, d * d, b2[f]);
}

// Layer-2 edge scatter: half-warp per edge, lane = feature (16 == FOUT).
__global__ void k_scatter2(int E) {
    long long idx = (long long)blockIdx.x * blockDim.x + threadIdx.x;
    if (idx >= (long long)E * FOUT) return;
    int e = (int)(idx >> 4);
    int f = (int)(idx & 15);
    int r = g_row[e];
    int c = g_col[e];
    float n = g_dinv[r] * g_dinv[c];
    atomicAdd(&g_o2[c * FOUT + f], g_h2[r * FOUT + f] * n);
}

// out = relu(o2) @ fc_W + fc_b
__global__ void k_final(const float* __restrict__ fcW,
                        const float* __restrict__ fcb,
                        float* __restrict__ out) {
    int i = blockIdx.x * blockDim.x + threadIdx.x;
    if (i >= N_NODES) return;
    float acc = __ldg(&fcb[0]);
    #pragma unroll
    for (int k = 0; k < FOUT; k++)
        acc = fmaf(fmaxf(g_o2[i * FOUT + k], 0.0f), __ldg(&fcW[k]), acc);
    out[i] = acc;
}

// ---------------- launch ----------------
extern "C" void kernel_launch(void* const* d_in, const int* in_sizes, int n_in,
                              void* d_out, int out_size) {
    const void*  edge = d_in[0];                     // [2, E] int64-or-int32
    const float* x    = (const float*)d_in[1];       // [N, 16]
    const float* W1   = (const float*)d_in[2];       // [16, 32]
    const float* b1   = (const float*)d_in[3];       // [32]
    const float* W2   = (const float*)d_in[4];       // [32, 16]
    const float* b2   = (const float*)d_in[5];       // [16]
    const float* fcW  = (const float*)d_in[6];       // [16, 1]
    const float* fcb  = (const float*)d_in[7];       // [1]
    float* out = (float*)d_out;

    const int E = in_sizes[0] / 2;                   // element count / 2 (both dtypes)
    const int T = 256;

    k_init_deg<<<(N_NODES + T - 1) / T, T>>>();
    k_detect<<<1, 256>>>((const unsigned int*)edge);
    k_edges<<<(E + T - 1) / T, T>>>(edge, E);
    k_rsqrt<<<(N_NODES + T - 1) / T, T>>>();
    k_lin1<<<(N_NODES * FMID + T - 1) / T, T>>>(x, W1, b1);
    {
        long long total = (long long)E * FMID;
        k_scatter1<<<(unsigned)((total + T - 1) / T), T>>>(E);
    }
    k_lin2<<<(N_NODES * FOUT + T - 1) / T, T>>>(W2, b2);
    {
        long long total = (long long)E * FOUT;
        k_scatter2<<<(unsigned)((total + T - 1) / T), T>>>(E);
    }
    k_final<<<(N_NODES + T - 1) / T, T>>>(fcW, fcb, out);
}

// round 3
// speedup vs baseline: 1.0524x; 1.0524x over previous
#include <cuda_runtime.h>

#define N_NODES 100000
#define E_EDGES 1600000
#define FIN  16
#define FMID 32
#define FOUT 16

// ---------------- device scratch (no allocations allowed) ----------------
__device__ int   g_row[E_EDGES];
__device__ int   g_col[E_EDGES];
__device__ float g_dinv[N_NODES];           // deg accumulator, then dinv in place
__device__ float g_h1[N_NODES * FMID];      // x @ W1
__device__ float g_o1[N_NODES * FMID];      // segment-sum + b1 (pre-relu)
__device__ float g_h2[N_NODES * FOUT];      // relu(o1) @ W2
__device__ float g_o2[N_NODES * FOUT];      // segment-sum + b2 (pre-relu)
__device__ int   g_is64;                    // edge_index dtype flag

// v4 float reduction (sm_90+): one L2 atomic op for 4 floats
__device__ __forceinline__ void red_add_v4(float* p, float a, float b, float c, float d) {
    asm volatile("red.global.add.v4.f32 [%0], {%1,%2,%3,%4};"
                 :: "l"(p), "f"(a), "f"(b), "f"(c), "f"(d) : "memory");
}

// ---------------- kernels ----------------

// deg init = 1.0 (self-loop on every node); block 0 also detects dtype.
__global__ void k_init(const unsigned int* __restrict__ words) {
    int i = blockIdx.x * blockDim.x + threadIdx.x;
    if (i < N_NODES) g_dinv[i] = 1.0f;
    if (blockIdx.x == 0) {
        __shared__ unsigned int s_or;
        if (threadIdx.x == 0) s_or = 0u;
        __syncthreads();
        unsigned int acc = 0u;
        for (int j = threadIdx.x; j < 8192; j += blockDim.x)
            acc |= words[2 * j + 1];          // odd words all-zero <=> int64
        atomicOr(&s_or, acc);
        __syncthreads();
        if (threadIdx.x == 0) g_is64 = (s_or == 0u) ? 1 : 0;
    }
}

// Convert edges to int32 scratch + accumulate degree of col (RED, no return).
__global__ void k_edges(const void* __restrict__ edge_raw, int E) {
    int e = blockIdx.x * blockDim.x + threadIdx.x;
    if (e >= E) return;
    int r, c;
    if (g_is64) {
        const long long* p = (const long long*)edge_raw;
        r = (int)p[e];
        c = (int)p[E + e];
    } else {
        const int* p = (const int*)edge_raw;
        r = p[e];
        c = p[E + e];
    }
    g_row[e] = r;
    g_col[e] = c;
    atomicAdd(&g_dinv[c], 1.0f);
}

// h1 = x @ W1 ; o1 = h1 * dinv^2 + b1 ; also converts deg -> dinv in place.
// thread = (node, feature): 32 threads per node == exactly one warp.
__global__ void k_lin1(const float* __restrict__ x,
                       const float* __restrict__ W1,
                       const float* __restrict__ b1) {
    __shared__ float sW[FIN * FMID];
    for (int t = threadIdx.x; t < FIN * FMID; t += blockDim.x) sW[t] = W1[t];
    __syncthreads();
    int idx = blockIdx.x * blockDim.x + threadIdx.x;
    if (idx >= N_NODES * FMID) return;
    int i = idx >> 5;         // FMID == 32
    int f = idx & 31;
    float deg = g_dinv[i];    // all 32 lanes of this warp read node i's deg
    float d = rsqrtf(deg);
    __syncwarp();             // all reads done before lane-0 overwrites
    if (f == 0) g_dinv[i] = d;
    float acc = 0.0f;
    #pragma unroll
    for (int k = 0; k < FIN; k++)
        acc = fmaf(x[i * FIN + k], sW[k * FMID + f], acc);
    g_h1[idx] = acc;
    g_o1[idx] = fmaf(acc, d * d, b1[f]);
}

// Layer-1 edge scatter: 8 threads per edge, each owns a float4 (FMID=32).
__global__ void k_scatter1(int E) {
    int idx = blockIdx.x * blockDim.x + threadIdx.x;
    if (idx >= E * 8) return;
    int e = idx >> 3;
    int q = idx & 7;
    int r = g_row[e];
    int c = g_col[e];
    float n = g_dinv[r] * g_dinv[c];
    float4 h = ((const float4*)g_h1)[r * 8 + q];
    red_add_v4(&g_o1[c * FMID + q * 4], h.x * n, h.y * n, h.z * n, h.w * n);
}

// h2 = relu(o1) @ W2 ; o2 = h2 * dinv^2 + b2
__global__ void k_lin2(const float* __restrict__ W2,
                       const float* __restrict__ b2) {
    __shared__ float sW[FMID * FOUT];
    for (int t = threadIdx.x; t < FMID * FOUT; t += blockDim.x) sW[t] = W2[t];
    __syncthreads();
    int idx = blockIdx.x * blockDim.x + threadIdx.x;
    if (idx >= N_NODES * FOUT) return;
    int i = idx >> 4;         // FOUT == 16
    int f = idx & 15;
    float acc = 0.0f;
    #pragma unroll
    for (int k = 0; k < FMID; k++) {
        float v = fmaxf(g_o1[i * FMID + k], 0.0f);
        acc = fmaf(v, sW[k * FOUT + f], acc);
    }
    g_h2[idx] = acc;
    float d = g_dinv[i];      // already dinv
    g_o2[idx] = fmaf(acc, d * d, b2[f]);
}

// Layer-2 edge scatter: 4 threads per edge, each owns a float4 (FOUT=16).
__global__ void k_scatter2(int E) {
    int idx = blockIdx.x * blockDim.x + threadIdx.x;
    if (idx >= E * 4) return;
    int e = idx >> 2;
    int q = idx & 3;
    int r = g_row[e];
    int c = g_col[e];
    float n = g_dinv[r] * g_dinv[c];
    float4 h = ((const float4*)g_h2)[r * 4 + q];
    red_add_v4(&g_o2[c * FOUT + q * 4], h.x * n, h.y * n, h.z * n, h.w * n);
}

// out = relu(o2) @ fc_W + fc_b
__global__ void k_final(const float* __restrict__ fcW,
                        const float* __restrict__ fcb,
                        float* __restrict__ out) {
    int i = blockIdx.x * blockDim.x + threadIdx.x;
    if (i >= N_NODES) return;
    float acc = __ldg(&fcb[0]);
    #pragma unroll
    for (int k = 0; k < FOUT; k++)
        acc = fmaf(fmaxf(g_o2[i * FOUT + k], 0.0f), __ldg(&fcW[k]), acc);
    out[i] = acc;
}

// ---------------- launch ----------------
extern "C" void kernel_launch(void* const* d_in, const int* in_sizes, int n_in,
                              void* d_out, int out_size) {
    const void*  edge = d_in[0];                     // [2, E] int64-or-int32
    const float* x    = (const float*)d_in[1];
    const float* W1   = (const float*)d_in[2];
    const float* b1   = (const float*)d_in[3];
    const float* W2   = (const float*)d_in[4];
    const float* b2   = (const float*)d_in[5];
    const float* fcW  = (const float*)d_in[6];
    const float* fcb  = (const float*)d_in[7];
    float* out = (float*)d_out;

    const int E = in_sizes[0] / 2;
    const int T = 256;

    k_init<<<(N_NODES + T - 1) / T, T>>>((const unsigned int*)edge);
    k_edges<<<(E + T - 1) / T, T>>>(edge, E);
    k_lin1<<<(N_NODES * FMID + T - 1) / T, T>>>(x, W1, b1);
    k_scatter1<<<(E * 8 + T - 1) / T, T>>>(E);
    k_lin2<<<(N_NODES * FOUT + T - 1) / T, T>>>(W2, b2);
    k_scatter2<<<(E * 4 + T - 1) / T, T>>>(E);
    k_final<<<(N_NODES + T - 1) / T, T>>>(fcW, fcb, out);
}

// round 6
// speedup vs baseline: 1.7752x; 1.6868x over previous
#include <cuda_runtime.h>

#define N_NODES 100000
#define E_EDGES 1600000
#define FIN  16
#define FMID 32
#define FOUT 16

// ---------------- device scratch ----------------
__device__ int   g_row[E_EDGES];
__device__ int   g_col[E_EDGES];
__device__ float g_dinv[N_NODES];           // deg accumulator, then dinv in place
__device__ float g_h1s[N_NODES * FMID];     // (x @ W1) * dinv  (gather source)
__device__ float g_u1 [N_NODES * FMID];     // accumulator, init = h1s (self-loop)
__device__ float g_h2s[N_NODES * FOUT];     // (relu(o1) @ W2) * dinv
__device__ float g_u2 [N_NODES * FOUT];     // accumulator, init = h2s
__device__ int   g_is64;

// v4 float reduction (sm_90+): one L2 op for 4 floats
__device__ __forceinline__ void red_add_v4(float* p, float4 v) {
    asm volatile("red.global.add.v4.f32 [%0], {%1,%2,%3,%4};"
                 :: "l"(p), "f"(v.x), "f"(v.y), "f"(v.z), "f"(v.w) : "memory");
}

// ---------------- kernels ----------------

__global__ void k_init(const unsigned int* __restrict__ words) {
    int i = blockIdx.x * blockDim.x + threadIdx.x;
    if (i < N_NODES) g_dinv[i] = 1.0f;      // self-loop
    if (blockIdx.x == 0) {
        __shared__ unsigned int s_or;
        if (threadIdx.x == 0) s_or = 0u;
        __syncthreads();
        unsigned int acc = 0u;
        for (int j = threadIdx.x; j < 8192; j += blockDim.x)
            acc |= words[2 * j + 1];        // odd words all-zero <=> int64
        atomicOr(&s_or, acc);
        __syncthreads();
        if (threadIdx.x == 0) g_is64 = (s_or == 0u) ? 1 : 0;
    }
}

__global__ void k_edges(const void* __restrict__ edge_raw, int E) {
    int e = blockIdx.x * blockDim.x + threadIdx.x;
    if (e >= E) return;
    int r, c;
    if (g_is64) {
        const long long* p = (const long long*)edge_raw;
        r = (int)p[e];
        c = (int)p[E + e];
    } else {
        const int* p = (const int*)edge_raw;
        r = p[e];
        c = p[E + e];
    }
    g_row[e] = r;
    g_col[e] = c;
    atomicAdd(&g_dinv[c], 1.0f);
}

// dinv finalize + h1s = (x@W1)*dinv, u1 = h1s.  32 threads per node (1 warp).
__global__ void k_lin1(const float* __restrict__ x,
                       const float* __restrict__ W1) {
    __shared__ float sW[FIN * FMID];
    for (int t = threadIdx.x; t < FIN * FMID; t += blockDim.x) sW[t] = W1[t];
    __syncthreads();
    int idx = blockIdx.x * blockDim.x + threadIdx.x;
    if (idx >= N_NODES * FMID) return;
    int i = idx >> 5;
    int f = idx & 31;
    float d = rsqrtf(g_dinv[i]);
    __syncwarp();
    if (f == 0) g_dinv[i] = d;
    float acc = 0.0f;
    #pragma unroll
    for (int k = 0; k < FIN; k++)
        acc = fmaf(x[i * FIN + k], sW[k * FMID + f], acc);
    acc *= d;
    g_h1s[idx] = acc;
    g_u1[idx]  = acc;      // self-loop term pre-seeded
}

// Layer-1 scatter: u1[col] += h1s[row]. 8 threads/edge, float4 each. No norms.
__global__ void k_scatter1(int E) {
    int idx = blockIdx.x * blockDim.x + threadIdx.x;
    if (idx >= E * 8) return;
    int e = idx >> 3;
    int q = idx & 7;
    int r = g_row[e];
    int c = g_col[e];
    float4 h = ((const float4*)g_h1s)[r * 8 + q];
    red_add_v4(&g_u1[c * FMID + q * 4], h);
}

// o1 = dinv*u1 + b1 ; relu ; h2s = (v @ W2)*dinv ; u2 = h2s.
// 16 threads per node.
__global__ void k_lin2(const float* __restrict__ W2,
                       const float* __restrict__ b1) {
    __shared__ float sW[FMID * FOUT];
    __shared__ float sb[FMID];
    for (int t = threadIdx.x; t < FMID * FOUT; t += blockDim.x) sW[t] = W2[t];
    for (int t = threadIdx.x; t < FMID; t += blockDim.x) sb[t] = b1[t];
    __syncthreads();
    int idx = blockIdx.x * blockDim.x + threadIdx.x;
    if (idx >= N_NODES * FOUT) return;
    int i = idx >> 4;
    int f = idx & 15;
    float d = g_dinv[i];
    float acc = 0.0f;
    #pragma unroll
    for (int k = 0; k < FMID; k++) {
        float v = fmaxf(fmaf(g_u1[i * FMID + k], d, sb[k]), 0.0f);
        acc = fmaf(v, sW[k * FOUT + f], acc);
    }
    acc *= d;
    g_h2s[idx] = acc;
    g_u2[idx]  = acc;
}

// Layer-2 scatter: u2[col] += h2s[row]. 4 threads/edge, float4 each.
__global__ void k_scatter2(int E) {
    int idx = blockIdx.x * blockDim.x + threadIdx.x;
    if (idx >= E * 4) return;
    int e = idx >> 2;
    int q = idx & 3;
    int r = g_row[e];
    int c = g_col[e];
    float4 h = ((const float4*)g_h2s)[r * 4 + q];
    red_add_v4(&g_u2[c * FOUT + q * 4], h);
}

// out = relu(dinv*u2 + b2) @ fc_W + fc_b
__global__ void k_final(const float* __restrict__ fcW,
                        const float* __restrict__ fcb,
                        const float* __restrict__ b2,
                        float* __restrict__ out) {
    int i = blockIdx.x * blockDim.x + threadIdx.x;
    if (i >= N_NODES) return;
    float d = g_dinv[i];
    float acc = __ldg(&fcb[0]);
    #pragma unroll
    for (int k = 0; k < FOUT; k++) {
        float v = fmaxf(fmaf(g_u2[i * FOUT + k], d, __ldg(&b2[k])), 0.0f);
        acc = fmaf(v, __ldg(&fcW[k]), acc);
    }
    out[i] = acc;
}

// ---------------- launch ----------------
extern "C" void kernel_launch(void* const* d_in, const int* in_sizes, int n_in,
                              void* d_out, int out_size) {
    const void*  edge = d_in[0];
    const float* x    = (const float*)d_in[1];
    const float* W1   = (const float*)d_in[2];
    const float* b1   = (const float*)d_in[3];
    const float* W2   = (const float*)d_in[4];
    const float* b2   = (const float*)d_in[5];
    const float* fcW  = (const float*)d_in[6];
    const float* fcb  = (const float*)d_in[7];
    float* out = (float*)d_out;

    const int E = in_sizes[0] / 2;
    const int T = 256;

    k_init<<<(N_NODES + T - 1) / T, T>>>((const unsigned int*)edge);
    k_edges<<<(E + T - 1) / T, T>>>(edge, E);
    k_lin1<<<(N_NODES * FMID + T - 1) / T, T>>>(x, W1);
    k_scatter1<<<(E * 8 + T - 1) / T, T>>>(E);
    k_lin2<<<(N_NODES * FOUT + T - 1) / T, T>>>(W2, b1);
    k_scatter2<<<(E * 4 + T - 1) / T, T>>>(E);
    k_final<<<(N_NODES + T - 1) / T, T>>>(fcW, fcb, b2, out);
}